// round 1
// baseline (speedup 1.0000x reference)
#include <cuda_runtime.h>
#include <math.h>

#define T_TOK   4096
#define DMODEL  512
#define NEXP    8
#define DFF     2048
#define NASSIGN (T_TOK * 2)

// ---------------- device scratch (static, allowed) ----------------
__device__ float g_xn[T_TOK * DMODEL];       // 8 MB  normalized input
__device__ float g_h[(size_t)NASSIGN * DFF]; // 64 MB gelu(xn@W1+b1) per assignment
__device__ float g_o[(size_t)NASSIGN * DMODEL]; // 16 MB conf*(h@W2+b2) per assignment
__device__ int   g_cnt[NEXP];
__device__ int   g_list[NEXP * T_TOK];       // assignment ids (t*2+k) per expert
__device__ float g_conf[NASSIGN];

// ---------------- K0: zero counters ----------------
__global__ void k_zero() {
    if (threadIdx.x < NEXP) g_cnt[threadIdx.x] = 0;
}

// ---------------- K1: LayerNorm + router (one block per token) ----------------
__global__ void k_ln_router(const float* __restrict__ x, const float* __restrict__ Wg,
                            const float* __restrict__ ln_g, const float* __restrict__ ln_b) {
    int t = blockIdx.x;
    int tid = threadIdx.x;              // 256 threads
    const float* xr = x + (size_t)t * DMODEL;

    __shared__ float s_xn[DMODEL];
    __shared__ float sred[256];
    __shared__ float wsum[8][8];

    float v0 = xr[tid], v1 = xr[tid + 256];

    // mean
    sred[tid] = v0 + v1;
    __syncthreads();
    for (int off = 128; off > 0; off >>= 1) {
        if (tid < off) sred[tid] += sred[tid + off];
        __syncthreads();
    }
    float mean = sred[0] * (1.0f / DMODEL);
    __syncthreads();

    float d0 = v0 - mean, d1 = v1 - mean;
    sred[tid] = d0 * d0 + d1 * d1;
    __syncthreads();
    for (int off = 128; off > 0; off >>= 1) {
        if (tid < off) sred[tid] += sred[tid + off];
        __syncthreads();
    }
    float var = sred[0] * (1.0f / DMODEL);
    float rstd = rsqrtf(var + 1e-5f);
    __syncthreads();

    float xn0 = d0 * rstd * ln_g[tid]       + ln_b[tid];
    float xn1 = d1 * rstd * ln_g[tid + 256] + ln_b[tid + 256];
    s_xn[tid] = xn0;
    s_xn[tid + 256] = xn1;
    g_xn[(size_t)t * DMODEL + tid]       = xn0;
    g_xn[(size_t)t * DMODEL + tid + 256] = xn1;
    __syncthreads();

    // router logits: xn (512) @ Wg (512x8)
    float p[NEXP];
#pragma unroll
    for (int e = 0; e < NEXP; e++) p[e] = 0.0f;
    for (int d = tid; d < DMODEL; d += 256) {
        float v = s_xn[d];
        const float* wr = Wg + (size_t)d * NEXP;
#pragma unroll
        for (int e = 0; e < NEXP; e++) p[e] += v * wr[e];
    }
    int lane = tid & 31, wid = tid >> 5;
#pragma unroll
    for (int e = 0; e < NEXP; e++) {
        for (int off = 16; off > 0; off >>= 1)
            p[e] += __shfl_down_sync(0xffffffffu, p[e], off);
    }
    if (lane == 0) {
#pragma unroll
        for (int e = 0; e < NEXP; e++) wsum[wid][e] = p[e];
    }
    __syncthreads();

    if (tid == 0) {
        float lg[NEXP];
#pragma unroll
        for (int e = 0; e < NEXP; e++) {
            float s = 0.0f;
#pragma unroll
            for (int w = 0; w < 8; w++) s += wsum[w][e];
            lg[e] = s;
        }
        // top-2 (first index on ties, like jax.lax.top_k)
        int i0 = 0;
#pragma unroll
        for (int e = 1; e < NEXP; e++) if (lg[e] > lg[i0]) i0 = e;
        int i1 = -1;
#pragma unroll
        for (int e = 0; e < NEXP; e++) {
            if (e == i0) continue;
            if (i1 < 0 || lg[e] > lg[i1]) i1 = e;
        }
        // renormalized confidence over the two selected logits
        float c0 = 1.0f / (1.0f + expf(lg[i1] - lg[i0]));
        float c1 = 1.0f - c0;
        int a0 = t * 2, a1 = t * 2 + 1;
        g_conf[a0] = c0;
        g_conf[a1] = c1;
        int p0 = atomicAdd(&g_cnt[i0], 1);
        g_list[i0 * T_TOK + p0] = a0;
        int p1 = atomicAdd(&g_cnt[i1], 1);
        g_list[i1 * T_TOK + p1] = a1;
    }
}

// ---------------- K2: per-expert GEMM1 + GELU ----------------
// C[rows_e, DFF] = gelu( gather(xn) @ W1[e] + b1[e] )
// BM=64, BN=64, BK=16, 256 threads, 4x4 microtile
__global__ void k_ffn1(const float* __restrict__ W1, const float* __restrict__ b1) {
    int e = blockIdx.z;
    int cnt = g_cnt[e];
    int row0 = blockIdx.y * 64;
    if (row0 >= cnt) return;
    int n0 = blockIdx.x * 64;
    int tid = threadIdx.x;
    int tx = tid & 15, ty = tid >> 4;

    __shared__ float As[16][68];
    __shared__ float Bs[16][64];
    __shared__ int   s_aid[64];

    if (tid < 64) {
        int r = row0 + tid;
        s_aid[tid] = (r < cnt) ? g_list[e * T_TOK + r] : -1;
    }
    __syncthreads();

    const float* Wb = W1 + (size_t)e * DMODEL * DFF;
    float acc[4][4] = {};

    for (int k0 = 0; k0 < DMODEL; k0 += 16) {
#pragma unroll
        for (int i = tid; i < 64 * 16; i += 256) {
            int r = i >> 4, kk = i & 15;
            int aid = s_aid[r];
            As[kk][r] = (aid >= 0) ? g_xn[(size_t)(aid >> 1) * DMODEL + k0 + kk] : 0.0f;
        }
#pragma unroll
        for (int i = tid; i < 16 * 64; i += 256) {
            int kk = i >> 6, n = i & 63;
            Bs[kk][n] = Wb[(size_t)(k0 + kk) * DFF + n0 + n];
        }
        __syncthreads();
#pragma unroll
        for (int kk = 0; kk < 16; kk++) {
            float a[4], b[4];
#pragma unroll
            for (int i = 0; i < 4; i++) a[i] = As[kk][ty * 4 + i];
#pragma unroll
            for (int j = 0; j < 4; j++) b[j] = Bs[kk][tx * 4 + j];
#pragma unroll
            for (int i = 0; i < 4; i++)
#pragma unroll
                for (int j = 0; j < 4; j++) acc[i][j] += a[i] * b[j];
        }
        __syncthreads();
    }

#pragma unroll
    for (int i = 0; i < 4; i++) {
        int r = row0 + ty * 4 + i;
        if (r >= cnt) continue;
        int aid = s_aid[ty * 4 + i];
        float* hrow = g_h + (size_t)aid * DFF;
#pragma unroll
        for (int j = 0; j < 4; j++) {
            int n = n0 + tx * 4 + j;
            float v = acc[i][j] + b1[e * DFF + n];
            float inner = 0.7978845608028654f * (v + 0.044715f * v * v * v);
            hrow[n] = 0.5f * v * (1.0f + tanhf(inner));
        }
    }
}

// ---------------- K3: per-expert GEMM2, scale by conf ----------------
// o[aid, DMODEL] = conf[aid] * ( h[aid] @ W2[e] + b2[e] )
__global__ void k_ffn2(const float* __restrict__ W2, const float* __restrict__ b2) {
    int e = blockIdx.z;
    int cnt = g_cnt[e];
    int row0 = blockIdx.y * 64;
    if (row0 >= cnt) return;
    int n0 = blockIdx.x * 64;
    int tid = threadIdx.x;
    int tx = tid & 15, ty = tid >> 4;

    __shared__ float As[16][68];
    __shared__ float Bs[16][64];
    __shared__ int   s_aid[64];

    if (tid < 64) {
        int r = row0 + tid;
        s_aid[tid] = (r < cnt) ? g_list[e * T_TOK + r] : -1;
    }
    __syncthreads();

    const float* Wb = W2 + (size_t)e * DFF * DMODEL;
    float acc[4][4] = {};

    for (int k0 = 0; k0 < DFF; k0 += 16) {
#pragma unroll
        for (int i = tid; i < 64 * 16; i += 256) {
            int r = i >> 4, kk = i & 15;
            int aid = s_aid[r];
            As[kk][r] = (aid >= 0) ? g_h[(size_t)aid * DFF + k0 + kk] : 0.0f;
        }
#pragma unroll
        for (int i = tid; i < 16 * 64; i += 256) {
            int kk = i >> 6, n = i & 63;
            Bs[kk][n] = Wb[(size_t)(k0 + kk) * DMODEL + n0 + n];
        }
        __syncthreads();
#pragma unroll
        for (int kk = 0; kk < 16; kk++) {
            float a[4], b[4];
#pragma unroll
            for (int i = 0; i < 4; i++) a[i] = As[kk][ty * 4 + i];
#pragma unroll
            for (int j = 0; j < 4; j++) b[j] = Bs[kk][tx * 4 + j];
#pragma unroll
            for (int i = 0; i < 4; i++)
#pragma unroll
                for (int j = 0; j < 4; j++) acc[i][j] += a[i] * b[j];
        }
        __syncthreads();
    }

#pragma unroll
    for (int i = 0; i < 4; i++) {
        int r = row0 + ty * 4 + i;
        if (r >= cnt) continue;
        int aid = s_aid[ty * 4 + i];
        float cf = g_conf[aid];
        float* orow = g_o + (size_t)aid * DMODEL;
#pragma unroll
        for (int j = 0; j < 4; j++) {
            int n = n0 + tx * 4 + j;
            orow[n] = cf * (acc[i][j] + b2[e * DMODEL + n]);
        }
    }
}

// ---------------- K4: combine + residual + post-LN ----------------
__global__ void k_combine(const float* __restrict__ x, const float* __restrict__ out_g,
                          const float* __restrict__ out_b, float* __restrict__ out) {
    int t = blockIdx.x;
    int tid = threadIdx.x;  // 256
    const float* o0 = g_o + (size_t)(t * 2) * DMODEL;
    const float* o1 = o0 + DMODEL;
    const float* xr = x + (size_t)t * DMODEL;

    __shared__ float sred[256];

    float y0 = xr[tid]       + o0[tid]       + o1[tid];
    float y1 = xr[tid + 256] + o0[tid + 256] + o1[tid + 256];

    sred[tid] = y0 + y1;
    __syncthreads();
    for (int off = 128; off > 0; off >>= 1) {
        if (tid < off) sred[tid] += sred[tid + off];
        __syncthreads();
    }
    float mean = sred[0] * (1.0f / DMODEL);
    __syncthreads();

    float d0 = y0 - mean, d1 = y1 - mean;
    sred[tid] = d0 * d0 + d1 * d1;
    __syncthreads();
    for (int off = 128; off > 0; off >>= 1) {
        if (tid < off) sred[tid] += sred[tid + off];
        __syncthreads();
    }
    float var = sred[0] * (1.0f / DMODEL);
    float rstd = rsqrtf(var + 1e-5f);

    float* orow = out + (size_t)t * DMODEL;
    orow[tid]       = d0 * rstd * out_g[tid]       + out_b[tid];
    orow[tid + 256] = d1 * rstd * out_g[tid + 256] + out_b[tid + 256];
}

// ---------------- launch ----------------
extern "C" void kernel_launch(void* const* d_in, const int* in_sizes, int n_in,
                              void* d_out, int out_size) {
    const float* x     = (const float*)d_in[0];
    const float* Wg    = (const float*)d_in[1];
    const float* W1    = (const float*)d_in[2];
    const float* b1    = (const float*)d_in[3];
    const float* W2    = (const float*)d_in[4];
    const float* b2    = (const float*)d_in[5];
    const float* ln_g  = (const float*)d_in[6];
    const float* ln_b  = (const float*)d_in[7];
    const float* out_g = (const float*)d_in[8];
    const float* out_b = (const float*)d_in[9];
    float* out = (float*)d_out;

    k_zero<<<1, 32>>>();
    k_ln_router<<<T_TOK, 256>>>(x, Wg, ln_g, ln_b);

    dim3 g1(DFF / 64, T_TOK / 64, NEXP);     // 32 x 64 x 8 (early-exit beyond cnt[e])
    k_ffn1<<<g1, 256>>>(W1, b1);

    dim3 g2(DMODEL / 64, T_TOK / 64, NEXP);  // 8 x 64 x 8
    k_ffn2<<<g2, 256>>>(W2, b2);

    k_combine<<<T_TOK, 256>>>(x, out_g, out_b, out);
}

// round 3
// speedup vs baseline: 7.6861x; 7.6861x over previous
#include <cuda_runtime.h>
#include <cuda_bf16.h>
#include <cstdint>
#include <math.h>

#define T_TOK   4096
#define DMODEL  512
#define NEXP    8
#define DFF     2048
#define NASSIGN (T_TOK * 2)

// ---------------- device scratch ----------------
__device__ __nv_bfloat16 g_xnb[T_TOK * DMODEL];                 // 4 MB  normalized input (bf16)
__device__ __nv_bfloat16 g_hb[(size_t)NASSIGN * DFF];           // 32 MB gelu activations (bf16)
__device__ float         g_o[(size_t)NASSIGN * DMODEL];         // 16 MB weighted expert outputs
__device__ __nv_bfloat16 g_w1b[(size_t)NEXP * DMODEL * DFF];    // 16.8 MB
__device__ __nv_bfloat16 g_w2b[(size_t)NEXP * DFF * DMODEL];    // 16.8 MB
__device__ int   g_cnt[NEXP];
__device__ int   g_list[NEXP * T_TOK];
__device__ float g_conf[NASSIGN];

// ---------------- helpers ----------------
__device__ __forceinline__ uint32_t sptr(const void* p) {
    return (uint32_t)__cvta_generic_to_shared(p);
}
__device__ __forceinline__ void cpasync16(uint32_t dst, const void* src, int srcsize) {
    asm volatile("cp.async.cg.shared.global [%0], [%1], 16, %2;\n"
                 :: "r"(dst), "l"(src), "r"(srcsize) : "memory");
}
__device__ __forceinline__ float gelu_f(float v) {
    float inner = 0.7978845608028654f * (v + 0.044715f * v * v * v);
    float t;
    asm("tanh.approx.f32 %0, %1;" : "=f"(t) : "f"(inner));
    return 0.5f * v * (1.0f + t);
}

#define LDSM4(R, addr) \
    asm volatile("ldmatrix.sync.aligned.m8n8.x4.shared.b16 {%0,%1,%2,%3}, [%4];" \
                 : "=r"(R[0]), "=r"(R[1]), "=r"(R[2]), "=r"(R[3]) : "r"(addr))
#define LDSM4T(R, addr) \
    asm volatile("ldmatrix.sync.aligned.m8n8.x4.trans.shared.b16 {%0,%1,%2,%3}, [%4];" \
                 : "=r"(R[0]), "=r"(R[1]), "=r"(R[2]), "=r"(R[3]) : "r"(addr))
#define MMA16816(C, A, B0, B1) \
    asm volatile("mma.sync.aligned.m16n8k16.row.col.f32.bf16.bf16.f32 " \
                 "{%0,%1,%2,%3}, {%4,%5,%6,%7}, {%8,%9}, {%0,%1,%2,%3};" \
                 : "+f"(C[0]), "+f"(C[1]), "+f"(C[2]), "+f"(C[3]) \
                 : "r"(A[0]), "r"(A[1]), "r"(A[2]), "r"(A[3]), "r"(B0), "r"(B1))

// ---------------- K0: zero counters ----------------
__global__ void k_zero() {
    if (threadIdx.x < NEXP) g_cnt[threadIdx.x] = 0;
}

// ---------------- Kc: convert weights fp32 -> bf16 ----------------
__global__ void k_cvt(const float* __restrict__ W1, const float* __restrict__ W2) {
    size_t i = ((size_t)blockIdx.x * 256 + threadIdx.x) * 4;
    const size_t N = (size_t)NEXP * DMODEL * DFF;
    if (i >= N) return;
    float4 a = *(const float4*)(W1 + i);
    float4 b = *(const float4*)(W2 + i);
    __nv_bfloat162* p1 = (__nv_bfloat162*)(g_w1b + i);
    __nv_bfloat162* p2 = (__nv_bfloat162*)(g_w2b + i);
    p1[0] = __floats2bfloat162_rn(a.x, a.y);
    p1[1] = __floats2bfloat162_rn(a.z, a.w);
    p2[0] = __floats2bfloat162_rn(b.x, b.y);
    p2[1] = __floats2bfloat162_rn(b.z, b.w);
}

// ---------------- K1: LayerNorm + router (one block per token) ----------------
__global__ void k_ln_router(const float* __restrict__ x, const float* __restrict__ Wg,
                            const float* __restrict__ ln_g, const float* __restrict__ ln_b) {
    int t = blockIdx.x;
    int tid = threadIdx.x;              // 256 threads
    const float* xr = x + (size_t)t * DMODEL;

    __shared__ float s_xn[DMODEL];
    __shared__ float sred[256];
    __shared__ float wsum[8][8];

    float v0 = xr[tid], v1 = xr[tid + 256];

    sred[tid] = v0 + v1;
    __syncthreads();
    for (int off = 128; off > 0; off >>= 1) {
        if (tid < off) sred[tid] += sred[tid + off];
        __syncthreads();
    }
    float mean = sred[0] * (1.0f / DMODEL);
    __syncthreads();

    float d0 = v0 - mean, d1 = v1 - mean;
    sred[tid] = d0 * d0 + d1 * d1;
    __syncthreads();
    for (int off = 128; off > 0; off >>= 1) {
        if (tid < off) sred[tid] += sred[tid + off];
        __syncthreads();
    }
    float var = sred[0] * (1.0f / DMODEL);
    float rstd = rsqrtf(var + 1e-5f);
    __syncthreads();

    float xn0 = d0 * rstd * ln_g[tid]       + ln_b[tid];
    float xn1 = d1 * rstd * ln_g[tid + 256] + ln_b[tid + 256];
    s_xn[tid] = xn0;
    s_xn[tid + 256] = xn1;
    g_xnb[(size_t)t * DMODEL + tid]       = __float2bfloat16(xn0);
    g_xnb[(size_t)t * DMODEL + tid + 256] = __float2bfloat16(xn1);
    __syncthreads();

    float p[NEXP];
#pragma unroll
    for (int e = 0; e < NEXP; e++) p[e] = 0.0f;
    for (int d = tid; d < DMODEL; d += 256) {
        float v = s_xn[d];
        const float* wr = Wg + (size_t)d * NEXP;
#pragma unroll
        for (int e = 0; e < NEXP; e++) p[e] += v * wr[e];
    }
    int lane = tid & 31, wid = tid >> 5;
#pragma unroll
    for (int e = 0; e < NEXP; e++) {
        for (int off = 16; off > 0; off >>= 1)
            p[e] += __shfl_down_sync(0xffffffffu, p[e], off);
    }
    if (lane == 0) {
#pragma unroll
        for (int e = 0; e < NEXP; e++) wsum[wid][e] = p[e];
    }
    __syncthreads();

    if (tid == 0) {
        float lg[NEXP];
#pragma unroll
        for (int e = 0; e < NEXP; e++) {
            float s = 0.0f;
#pragma unroll
            for (int w = 0; w < 8; w++) s += wsum[w][e];
            lg[e] = s;
        }
        int i0 = 0;
#pragma unroll
        for (int e = 1; e < NEXP; e++) if (lg[e] > lg[i0]) i0 = e;
        int i1 = -1;
#pragma unroll
        for (int e = 0; e < NEXP; e++) {
            if (e == i0) continue;
            if (i1 < 0 || lg[e] > lg[i1]) i1 = e;
        }
        float c0 = 1.0f / (1.0f + expf(lg[i1] - lg[i0]));
        float c1 = 1.0f - c0;
        int a0 = t * 2, a1 = t * 2 + 1;
        g_conf[a0] = c0;
        g_conf[a1] = c1;
        int p0 = atomicAdd(&g_cnt[i0], 1);
        g_list[i0 * T_TOK + p0] = a0;
        int p1 = atomicAdd(&g_cnt[i1], 1);
        g_list[i1 * T_TOK + p1] = a1;
    }
}

// ---------------- tensor-core routed GEMM ----------------
// BM=128, BN=128, BK=32, 256 threads (8 warps: 4m x 2n), warp tile 32x64.
// IS_FFN1: A = gathered g_xnb [cnt_e,512], B = g_w1b[e] [512,2048], out = gelu -> g_hb (bf16)
// else:    A = gathered g_hb  [cnt_e,2048], B = g_w2b[e] [2048,512], out = conf*(.) -> g_o (f32)
template<int KDIM, int LDB, bool IS_FFN1>
__global__ void __launch_bounds__(256, 2)
k_ffn(const float* __restrict__ bias) {
    const int e = blockIdx.z;
    const int cnt = g_cnt[e];
    const int row0 = blockIdx.y * 128;
    if (row0 >= cnt) return;
    const int n0 = blockIdx.x * 128;
    const int tid = threadIdx.x;
    const int lane = tid & 31, warp = tid >> 5;
    const int wm = warp & 3, wn = warp >> 2;

    // padded rows: A 56 bf16 (112B), B 136 bf16 (272B) -> conflict-free ldmatrix
    __shared__ __nv_bfloat16 As[2][128 * 56];
    __shared__ __nv_bfloat16 Bs[2][32 * 136];
    __shared__ float s_bias[128];
    __shared__ int   s_aid[128];

    const __nv_bfloat16* Asrc = IS_FFN1 ? g_xnb : g_hb;
    const __nv_bfloat16* W    = (IS_FFN1 ? g_w1b : g_w2b) + (size_t)e * KDIM * LDB;

    if (tid < 128) {
        int r = row0 + tid;
        s_aid[tid]  = (r < cnt) ? g_list[e * T_TOK + r] : -1;
        s_bias[tid] = bias[e * LDB + n0 + tid];
    }
    __syncthreads();

    const uint32_t sA = sptr(&As[0][0]);
    const uint32_t sB = sptr(&Bs[0][0]);

    // per-thread load slots: A chunks (tid, tid+256) of 512; B chunks (tid, tid+256) of 512
    const __nv_bfloat16* aptr[2]; int asz[2]; uint32_t aoff[2];
    const __nv_bfloat16* bptr[2]; uint32_t boff[2];
#pragma unroll
    for (int j = 0; j < 2; j++) {
        int c = tid + j * 256;
        int r = c >> 2;                 // 4 x 16B chunks per 32-col A row
        int cc = (c & 3) * 8;
        int aid = s_aid[r];
        if (aid >= 0) {
            size_t rowbase = IS_FFN1 ? (size_t)(aid >> 1) * DMODEL : (size_t)aid * DFF;
            aptr[j] = Asrc + rowbase + cc;
            asz[j] = 16;
        } else {
            aptr[j] = Asrc;
            asz[j] = 0;
        }
        aoff[j] = (uint32_t)(r * 56 + cc) * 2;

        int rb = c >> 4;                // 16 x 16B chunks per 128-col B row
        int ccb = (c & 15) * 8;
        bptr[j] = W + (size_t)rb * LDB + n0 + ccb;
        boff[j] = (uint32_t)(rb * 136 + ccb) * 2;
    }

    auto load_tiles = [&](int it, int stage) {
        int k0 = it * 32;
#pragma unroll
        for (int j = 0; j < 2; j++)
            cpasync16(sA + stage * 14336 + aoff[j], aptr[j] + k0, asz[j]);
#pragma unroll
        for (int j = 0; j < 2; j++)
            cpasync16(sB + stage * 8704 + boff[j], bptr[j] + (size_t)k0 * LDB, 16);
        asm volatile("cp.async.commit_group;\n" ::: "memory");
    };

    float acc[2][8][4] = {};

    constexpr int KT = KDIM / 32;
    load_tiles(0, 0);

#pragma unroll 1
    for (int it = 0; it < KT; it++) {
        if (it + 1 < KT) {
            load_tiles(it + 1, (it + 1) & 1);
            asm volatile("cp.async.wait_group 1;\n" ::: "memory");
        } else {
            asm volatile("cp.async.wait_group 0;\n" ::: "memory");
        }
        __syncthreads();

        const int st = it & 1;
        const uint32_t aBase = sA + st * 14336;
        const uint32_t bBase = sB + st * 8704;

#pragma unroll
        for (int kk = 0; kk < 32; kk += 16) {
            uint32_t a[2][4], b[4][4];
#pragma unroll
            for (int mi = 0; mi < 2; mi++) {
                int row = wm * 32 + mi * 16 + (lane & 15);
                uint32_t addr = aBase + (uint32_t)(row * 56 + kk) * 2 + (lane >> 4) * 16;
                LDSM4(a[mi], addr);
            }
#pragma unroll
            for (int nj = 0; nj < 4; nj++) {
                int krow = kk + (lane & 15);
                int col = wn * 64 + nj * 16 + (lane >> 4) * 8;
                uint32_t addr = bBase + (uint32_t)(krow * 136 + col) * 2;
                LDSM4T(b[nj], addr);
            }
#pragma unroll
            for (int mi = 0; mi < 2; mi++)
#pragma unroll
                for (int ni = 0; ni < 8; ni++)
                    MMA16816(acc[mi][ni], a[mi], b[ni >> 1][(ni & 1) * 2], b[ni >> 1][(ni & 1) * 2 + 1]);
        }
        __syncthreads();
    }

    // epilogue
#pragma unroll
    for (int mi = 0; mi < 2; mi++) {
#pragma unroll
        for (int half = 0; half < 2; half++) {
            int rl = wm * 32 + mi * 16 + (lane >> 2) + half * 8;
            if (row0 + rl >= cnt) continue;
            int aid = s_aid[rl];
            if (IS_FFN1) {
                __nv_bfloat16* hrow = g_hb + (size_t)aid * DFF + n0;
#pragma unroll
                for (int ni = 0; ni < 8; ni++) {
                    int col = wn * 64 + ni * 8 + (lane & 3) * 2;
                    float v0 = gelu_f(acc[mi][ni][half * 2 + 0] + s_bias[col]);
                    float v1 = gelu_f(acc[mi][ni][half * 2 + 1] + s_bias[col + 1]);
                    *(__nv_bfloat162*)(hrow + col) = __floats2bfloat162_rn(v0, v1);
                }
            } else {
                float cf = g_conf[aid];
                float* orow = g_o + (size_t)aid * DMODEL + n0;
#pragma unroll
                for (int ni = 0; ni < 8; ni++) {
                    int col = wn * 64 + ni * 8 + (lane & 3) * 2;
                    float2 v;
                    v.x = cf * (acc[mi][ni][half * 2 + 0] + s_bias[col]);
                    v.y = cf * (acc[mi][ni][half * 2 + 1] + s_bias[col + 1]);
                    *(float2*)(orow + col) = v;
                }
            }
        }
    }
}

// ---------------- K4: combine + residual + post-LN ----------------
__global__ void k_combine(const float* __restrict__ x, const float* __restrict__ out_g,
                          const float* __restrict__ out_b, float* __restrict__ out) {
    int t = blockIdx.x;
    int tid = threadIdx.x;  // 256
    const float* o0 = g_o + (size_t)(t * 2) * DMODEL;
    const float* o1 = o0 + DMODEL;
    const float* xr = x + (size_t)t * DMODEL;

    __shared__ float sred[256];

    float y0 = xr[tid]       + o0[tid]       + o1[tid];
    float y1 = xr[tid + 256] + o0[tid + 256] + o1[tid + 256];

    sred[tid] = y0 + y1;
    __syncthreads();
    for (int off = 128; off > 0; off >>= 1) {
        if (tid < off) sred[tid] += sred[tid + off];
        __syncthreads();
    }
    float mean = sred[0] * (1.0f / DMODEL);
    __syncthreads();

    float d0 = y0 - mean, d1 = y1 - mean;
    sred[tid] = d0 * d0 + d1 * d1;
    __syncthreads();
    for (int off = 128; off > 0; off >>= 1) {
        if (tid < off) sred[tid] += sred[tid + off];
        __syncthreads();
    }
    float var = sred[0] * (1.0f / DMODEL);
    float rstd = rsqrtf(var + 1e-5f);

    float* orow = out + (size_t)t * DMODEL;
    orow[tid]       = d0 * rstd * out_g[tid]       + out_b[tid];
    orow[tid + 256] = d1 * rstd * out_g[tid + 256] + out_b[tid + 256];
}

// ---------------- launch ----------------
extern "C" void kernel_launch(void* const* d_in, const int* in_sizes, int n_in,
                              void* d_out, int out_size) {
    const float* x     = (const float*)d_in[0];
    const float* Wg    = (const float*)d_in[1];
    const float* W1    = (const float*)d_in[2];
    const float* b1    = (const float*)d_in[3];
    const float* W2    = (const float*)d_in[4];
    const float* b2    = (const float*)d_in[5];
    const float* ln_g  = (const float*)d_in[6];
    const float* ln_b  = (const float*)d_in[7];
    const float* out_g = (const float*)d_in[8];
    const float* out_b = (const float*)d_in[9];
    float* out = (float*)d_out;

    k_zero<<<1, 32>>>();
    k_cvt<<<8192, 256>>>(W1, W2);
    k_ln_router<<<T_TOK, 256>>>(x, Wg, ln_g, ln_b);

    dim3 g1(DFF / 128, T_TOK / 128, NEXP);     // 16 x 32 x 8
    k_ffn<DMODEL, DFF, true><<<g1, 256>>>(b1);

    dim3 g2(DMODEL / 128, T_TOK / 128, NEXP);  // 4 x 32 x 8
    k_ffn<DFF, DMODEL, false><<<g2, 256>>>(b2);

    k_combine<<<T_TOK, 256>>>(x, out_g, out_b, out);
}

// round 8
// speedup vs baseline: 8.4718x; 1.1022x over previous
#include <cuda_runtime.h>
#include <cuda_bf16.h>
#include <cstdint>
#include <math.h>

#define T_TOK   4096
#define DMODEL  512
#define NEXP    8
#define DFF     2048
#define NASSIGN (T_TOK * 2)

// ---------------- device scratch ----------------
__device__ __nv_bfloat16 g_xnb[T_TOK * DMODEL];                 // 4 MB  normalized input (bf16)
__device__ __nv_bfloat16 g_hb[(size_t)NASSIGN * DFF];           // 32 MB gelu activations (bf16)
__device__ float         g_o[(size_t)NASSIGN * DMODEL];         // 16 MB weighted expert outputs
__device__ __nv_bfloat16 g_w1b[(size_t)NEXP * DMODEL * DFF];    // 16.8 MB
__device__ __nv_bfloat16 g_w2b[(size_t)NEXP * DFF * DMODEL];    // 16.8 MB
__device__ int   g_cnt[NEXP];
__device__ int   g_list[NEXP * T_TOK];
__device__ float g_conf[NASSIGN];

// ---------------- helpers ----------------
__device__ __forceinline__ uint32_t sptr(const void* p) {
    return (uint32_t)__cvta_generic_to_shared(p);
}
__device__ __forceinline__ void cpasync16(uint32_t dst, const void* src, int srcsize) {
    asm volatile("cp.async.cg.shared.global [%0], [%1], 16, %2;\n"
                 :: "r"(dst), "l"(src), "r"(srcsize) : "memory");
}
__device__ __forceinline__ float gelu_f(float v) {
    float inner = 0.7978845608028654f * (v + 0.044715f * v * v * v);
    float t;
    asm("tanh.approx.f32 %0, %1;" : "=f"(t) : "f"(inner));
    return 0.5f * v * (1.0f + t);
}

#define LDSM4(R, addr) \
    asm volatile("ldmatrix.sync.aligned.m8n8.x4.shared.b16 {%0,%1,%2,%3}, [%4];" \
                 : "=r"(R[0]), "=r"(R[1]), "=r"(R[2]), "=r"(R[3]) : "r"(addr))
#define LDSM4T(R, addr) \
    asm volatile("ldmatrix.sync.aligned.m8n8.x4.trans.shared.b16 {%0,%1,%2,%3}, [%4];" \
                 : "=r"(R[0]), "=r"(R[1]), "=r"(R[2]), "=r"(R[3]) : "r"(addr))
#define MMA16816(C, A, B0, B1) \
    asm volatile("mma.sync.aligned.m16n8k16.row.col.f32.bf16.bf16.f32 " \
                 "{%0,%1,%2,%3}, {%4,%5,%6,%7}, {%8,%9}, {%0,%1,%2,%3};" \
                 : "+f"(C[0]), "+f"(C[1]), "+f"(C[2]), "+f"(C[3]) \
                 : "r"(A[0]), "r"(A[1]), "r"(A[2]), "r"(A[3]), "r"(B0), "r"(B1))

// ---------------- Kc: convert weights fp32 -> bf16 (+ zero counters) ----------------
__global__ void k_cvt(const float* __restrict__ W1, const float* __restrict__ W2) {
    if (blockIdx.x == 0 && threadIdx.x < NEXP) g_cnt[threadIdx.x] = 0;
    size_t i = ((size_t)blockIdx.x * 256 + threadIdx.x) * 4;
    const size_t N = (size_t)NEXP * DMODEL * DFF;
    if (i >= N) return;
    float4 a = *(const float4*)(W1 + i);
    float4 b = *(const float4*)(W2 + i);
    __nv_bfloat162* p1 = (__nv_bfloat162*)(g_w1b + i);
    __nv_bfloat162* p2 = (__nv_bfloat162*)(g_w2b + i);
    p1[0] = __floats2bfloat162_rn(a.x, a.y);
    p1[1] = __floats2bfloat162_rn(a.z, a.w);
    p2[0] = __floats2bfloat162_rn(b.x, b.y);
    p2[1] = __floats2bfloat162_rn(b.z, b.w);
}

// ---------------- K1: LayerNorm + router, one WARP per token ----------------
// 256 threads = 8 warps = 8 tokens per block; 512 blocks.
__global__ void k_ln_router(const float* __restrict__ x, const float* __restrict__ Wg,
                            const float* __restrict__ ln_g, const float* __restrict__ ln_b) {
    const int warp = threadIdx.x >> 5, lane = threadIdx.x & 31;
    const int t = blockIdx.x * 8 + warp;
    const float* xr = x + (size_t)t * DMODEL;

    // load 16 strided elements per lane (coalesced)
    float v[16];
#pragma unroll
    for (int i = 0; i < 16; i++) v[i] = xr[lane + 32 * i];

    float s = 0.0f;
#pragma unroll
    for (int i = 0; i < 16; i++) s += v[i];
#pragma unroll
    for (int off = 16; off > 0; off >>= 1) s += __shfl_xor_sync(0xffffffffu, s, off);
    float mean = s * (1.0f / DMODEL);

    float s2 = 0.0f;
#pragma unroll
    for (int i = 0; i < 16; i++) { float d = v[i] - mean; s2 += d * d; }
#pragma unroll
    for (int off = 16; off > 0; off >>= 1) s2 += __shfl_xor_sync(0xffffffffu, s2, off);
    float rstd = rsqrtf(s2 * (1.0f / DMODEL) + 1e-5f);

    float xn[16];
    __nv_bfloat16* xnb = g_xnb + (size_t)t * DMODEL;
#pragma unroll
    for (int i = 0; i < 16; i++) {
        int d = lane + 32 * i;
        xn[i] = (v[i] - mean) * rstd * ln_g[d] + ln_b[d];
        xnb[d] = __float2bfloat16(xn[i]);
    }

    // router logits: xn(512) @ Wg(512x8); Wg is tiny (16KB) -> L1/L2 resident
    float p[NEXP];
#pragma unroll
    for (int e = 0; e < NEXP; e++) p[e] = 0.0f;
#pragma unroll
    for (int i = 0; i < 16; i++) {
        const float4* wr = (const float4*)(Wg + (size_t)(lane + 32 * i) * NEXP);
        float4 w0 = wr[0], w1 = wr[1];
        p[0] += xn[i] * w0.x; p[1] += xn[i] * w0.y;
        p[2] += xn[i] * w0.z; p[3] += xn[i] * w0.w;
        p[4] += xn[i] * w1.x; p[5] += xn[i] * w1.y;
        p[6] += xn[i] * w1.z; p[7] += xn[i] * w1.w;
    }
#pragma unroll
    for (int e = 0; e < NEXP; e++) {
#pragma unroll
        for (int off = 16; off > 0; off >>= 1)
            p[e] += __shfl_xor_sync(0xffffffffu, p[e], off);
    }

    if (lane == 0) {
        int i0 = 0;
#pragma unroll
        for (int e = 1; e < NEXP; e++) if (p[e] > p[i0]) i0 = e;
        int i1 = -1;
#pragma unroll
        for (int e = 0; e < NEXP; e++) {
            if (e == i0) continue;
            if (i1 < 0 || p[e] > p[i1]) i1 = e;
        }
        // renormalized confidence over the two selected logits
        float c0 = 1.0f / (1.0f + expf(p[i1] - p[i0]));
        float c1 = 1.0f - c0;
        int a0 = t * 2, a1 = t * 2 + 1;
        g_conf[a0] = c0;
        g_conf[a1] = c1;
        int p0 = atomicAdd(&g_cnt[i0], 1);
        g_list[i0 * T_TOK + p0] = a0;
        int p1 = atomicAdd(&g_cnt[i1], 1);
        g_list[i1 * T_TOK + p1] = a1;
    }
}

// ---------------- tensor-core routed GEMM (PROVEN R2 machinery, unchanged) ----------------
// BM=128, BN=128, BK=32, 256 threads (8 warps: 4m x 2n), warp tile 32x64.
// IS_FFN1: A = gathered g_xnb [cnt_e,512], B = g_w1b[e] [512,2048], out = gelu -> g_hb (bf16)
// else:    A = gathered g_hb  [cnt_e,2048], B = g_w2b[e] [2048,512], out = conf*(.) -> g_o (f32)
template<int KDIM, int LDB, bool IS_FFN1>
__global__ void __launch_bounds__(256, 2)
k_ffn(const float* __restrict__ bias) {
    const int e = blockIdx.z;
    const int cnt = g_cnt[e];
    const int row0 = blockIdx.y * 128;
    if (row0 >= cnt) return;
    const int n0 = blockIdx.x * 128;
    const int tid = threadIdx.x;
    const int lane = tid & 31, warp = tid >> 5;
    const int wm = warp & 3, wn = warp >> 2;

    // padded rows: A 56 bf16 (112B), B 136 bf16 (272B) -> conflict-free ldmatrix
    __shared__ __nv_bfloat16 As[2][128 * 56];
    __shared__ __nv_bfloat16 Bs[2][32 * 136];
    __shared__ float s_bias[128];
    __shared__ int   s_aid[128];

    const __nv_bfloat16* Asrc = IS_FFN1 ? g_xnb : g_hb;
    const __nv_bfloat16* W    = (IS_FFN1 ? g_w1b : g_w2b) + (size_t)e * KDIM * LDB;

    if (tid < 128) {
        int r = row0 + tid;
        s_aid[tid]  = (r < cnt) ? g_list[e * T_TOK + r] : -1;
        s_bias[tid] = bias[e * LDB + n0 + tid];
    }
    __syncthreads();

    const uint32_t sA = sptr(&As[0][0]);
    const uint32_t sB = sptr(&Bs[0][0]);

    // per-thread load slots: A chunks (tid, tid+256) of 512; B chunks (tid, tid+256) of 512
    const __nv_bfloat16* aptr[2]; int asz[2]; uint32_t aoff[2];
    const __nv_bfloat16* bptr[2]; uint32_t boff[2];
#pragma unroll
    for (int j = 0; j < 2; j++) {
        int c = tid + j * 256;
        int r = c >> 2;                 // 4 x 16B chunks per 32-col A row
        int cc = (c & 3) * 8;
        int aid = s_aid[r];
        if (aid >= 0) {
            size_t rowbase = IS_FFN1 ? (size_t)(aid >> 1) * DMODEL : (size_t)aid * DFF;
            aptr[j] = Asrc + rowbase + cc;
            asz[j] = 16;
        } else {
            aptr[j] = Asrc;
            asz[j] = 0;
        }
        aoff[j] = (uint32_t)(r * 56 + cc) * 2;

        int rb = c >> 4;                // 16 x 16B chunks per 128-col B row
        int ccb = (c & 15) * 8;
        bptr[j] = W + (size_t)rb * LDB + n0 + ccb;
        boff[j] = (uint32_t)(rb * 136 + ccb) * 2;
    }

    auto load_tiles = [&](int it, int stage) {
        int k0 = it * 32;
#pragma unroll
        for (int j = 0; j < 2; j++)
            cpasync16(sA + stage * 14336 + aoff[j], aptr[j] + k0, asz[j]);
#pragma unroll
        for (int j = 0; j < 2; j++)
            cpasync16(sB + stage * 8704 + boff[j], bptr[j] + (size_t)k0 * LDB, 16);
        asm volatile("cp.async.commit_group;\n" ::: "memory");
    };

    float acc[2][8][4] = {};

    constexpr int KT = KDIM / 32;
    load_tiles(0, 0);

#pragma unroll 1
    for (int it = 0; it < KT; it++) {
        if (it + 1 < KT) {
            load_tiles(it + 1, (it + 1) & 1);
            asm volatile("cp.async.wait_group 1;\n" ::: "memory");
        } else {
            asm volatile("cp.async.wait_group 0;\n" ::: "memory");
        }
        __syncthreads();

        const int st = it & 1;
        const uint32_t aBase = sA + st * 14336;
        const uint32_t bBase = sB + st * 8704;

#pragma unroll
        for (int kk = 0; kk < 32; kk += 16) {
            uint32_t a[2][4], b[4][4];
#pragma unroll
            for (int mi = 0; mi < 2; mi++) {
                int row = wm * 32 + mi * 16 + (lane & 15);
                uint32_t addr = aBase + (uint32_t)(row * 56 + kk) * 2 + (lane >> 4) * 16;
                LDSM4(a[mi], addr);
            }
#pragma unroll
            for (int nj = 0; nj < 4; nj++) {
                int krow = kk + (lane & 15);
                int col = wn * 64 + nj * 16 + (lane >> 4) * 8;
                uint32_t addr = bBase + (uint32_t)(krow * 136 + col) * 2;
                LDSM4T(b[nj], addr);
            }
#pragma unroll
            for (int mi = 0; mi < 2; mi++)
#pragma unroll
                for (int ni = 0; ni < 8; ni++)
                    MMA16816(acc[mi][ni], a[mi], b[ni >> 1][(ni & 1) * 2], b[ni >> 1][(ni & 1) * 2 + 1]);
        }
        __syncthreads();
    }

    // epilogue
#pragma unroll
    for (int mi = 0; mi < 2; mi++) {
#pragma unroll
        for (int half = 0; half < 2; half++) {
            int rl = wm * 32 + mi * 16 + (lane >> 2) + half * 8;
            if (row0 + rl >= cnt) continue;
            int aid = s_aid[rl];
            if (IS_FFN1) {
                __nv_bfloat16* hrow = g_hb + (size_t)aid * DFF + n0;
#pragma unroll
                for (int ni = 0; ni < 8; ni++) {
                    int col = wn * 64 + ni * 8 + (lane & 3) * 2;
                    float v0 = gelu_f(acc[mi][ni][half * 2 + 0] + s_bias[col]);
                    float v1 = gelu_f(acc[mi][ni][half * 2 + 1] + s_bias[col + 1]);
                    *(__nv_bfloat162*)(hrow + col) = __floats2bfloat162_rn(v0, v1);
                }
            } else {
                float cf = g_conf[aid];
                float* orow = g_o + (size_t)aid * DMODEL + n0;
#pragma unroll
                for (int ni = 0; ni < 8; ni++) {
                    int col = wn * 64 + ni * 8 + (lane & 3) * 2;
                    float2 v;
                    v.x = cf * (acc[mi][ni][half * 2 + 0] + s_bias[col]);
                    v.y = cf * (acc[mi][ni][half * 2 + 1] + s_bias[col + 1]);
                    *(float2*)(orow + col) = v;
                }
            }
        }
    }
}

// ---------------- K4: combine + residual + post-LN, one WARP per token ----------------
__global__ void k_combine(const float* __restrict__ x, const float* __restrict__ out_g,
                          const float* __restrict__ out_b, float* __restrict__ out) {
    const int warp = threadIdx.x >> 5, lane = threadIdx.x & 31;
    const int t = blockIdx.x * 8 + warp;
    const float* o0 = g_o + (size_t)(t * 2) * DMODEL;
    const float* o1 = o0 + DMODEL;
    const float* xr = x + (size_t)t * DMODEL;

    float y[16];
#pragma unroll
    for (int i = 0; i < 16; i++) {
        int d = lane + 32 * i;
        y[i] = xr[d] + o0[d] + o1[d];
    }

    float s = 0.0f;
#pragma unroll
    for (int i = 0; i < 16; i++) s += y[i];
#pragma unroll
    for (int off = 16; off > 0; off >>= 1) s += __shfl_xor_sync(0xffffffffu, s, off);
    float mean = s * (1.0f / DMODEL);

    float s2 = 0.0f;
#pragma unroll
    for (int i = 0; i < 16; i++) { float d = y[i] - mean; s2 += d * d; }
#pragma unroll
    for (int off = 16; off > 0; off >>= 1) s2 += __shfl_xor_sync(0xffffffffu, s2, off);
    float rstd = rsqrtf(s2 * (1.0f / DMODEL) + 1e-5f);

    float* orow = out + (size_t)t * DMODEL;
#pragma unroll
    for (int i = 0; i < 16; i++) {
        int d = lane + 32 * i;
        orow[d] = (y[i] - mean) * rstd * out_g[d] + out_b[d];
    }
}

// ---------------- launch ----------------
extern "C" void kernel_launch(void* const* d_in, const int* in_sizes, int n_in,
                              void* d_out, int out_size) {
    const float* x     = (const float*)d_in[0];
    const float* Wg    = (const float*)d_in[1];
    const float* W1    = (const float*)d_in[2];
    const float* b1    = (const float*)d_in[3];
    const float* W2    = (const float*)d_in[4];
    const float* b2    = (const float*)d_in[5];
    const float* ln_g  = (const float*)d_in[6];
    const float* ln_b  = (const float*)d_in[7];
    const float* out_g = (const float*)d_in[8];
    const float* out_b = (const float*)d_in[9];
    float* out = (float*)d_out;

    k_cvt<<<8192, 256>>>(W1, W2);
    k_ln_router<<<T_TOK / 8, 256>>>(x, Wg, ln_g, ln_b);

    dim3 g1(DFF / 128, T_TOK / 128, NEXP);     // 16 x 32 x 8
    k_ffn<DMODEL, DFF, true><<<g1, 256>>>(b1);

    dim3 g2(DMODEL / 128, T_TOK / 128, NEXP);  // 4 x 32 x 8
    k_ffn<DFF, DMODEL, false><<<g2, 256>>>(b2);

    k_combine<<<T_TOK / 8, 256>>>(x, out_g, out_b, out);
}